// round 15
// baseline (speedup 1.0000x reference)
#include <cuda_runtime.h>

#define Bdim 8
#define Ndim 8
#define Tdim 262144
#define ROWS (Bdim * Ndim)            // 64
#define CHUNKS 16                     // chunks per eIF row
#define EIF_BLOCKS (ROWS * CHUNKS)    // 1024
#define RECON_BLOCKS 256
#define THREADS 256
#define VEC_PER_CHUNK (Tdim / CHUNKS / 4)          // 4096 float4 per chunk
#define EIF_ITERS (VEC_PER_CHUNK / THREADS)        // 16
#define RECON_VEC (Bdim * Tdim / 4)                // 524288 float4 per array
#define RECON_ITERS (RECON_VEC / (RECON_BLOCKS * THREADS))  // 8

__device__ __forceinline__ void pdl_launch_dependents() {
    asm volatile("griddepcontrol.launch_dependents;" ::: "memory");
}
__device__ __forceinline__ void pdl_wait() {
    asm volatile("griddepcontrol.wait;" ::: "memory");
}

__device__ __forceinline__ float block_reduce(float v, float* sm) {
    #pragma unroll
    for (int o = 16; o > 0; o >>= 1) v += __shfl_down_sync(0xffffffffu, v, o);
    int warp = threadIdx.x >> 5;
    __syncthreads();
    if ((threadIdx.x & 31) == 0) sm[warp] = v;
    __syncthreads();
    if (warp == 0) {
        v = (threadIdx.x < (THREADS >> 5)) ? sm[threadIdx.x] : 0.0f;
        #pragma unroll
        for (int o = 4; o > 0; o >>= 1) v += __shfl_down_sync(0xffffffffu, v, o);
    }
    return v;
}

// Primary: zero the 4 outputs. launch_dependents FIRST so the main kernel
// launches immediately and this kernel's cost hides under it.
__global__ void zero_out_kernel(float* __restrict__ out) {
    pdl_launch_dependents();
    if (threadIdx.x < 4) out[threadIdx.x] = 0.0f;
}

__global__ void __launch_bounds__(THREADS, 6)
loss_main_kernel(const float* __restrict__ rr, const float* __restrict__ ri,
                 const float* __restrict__ tr, const float* __restrict__ ti,
                 const float* __restrict__ eIF, const float* __restrict__ tif,
                 const int* __restrict__ mode_mask, float* __restrict__ out)
{
    __shared__ float sm[THREADS / 32];
    __shared__ int cnt2[2];
    const int tid = threadIdx.x;
    const int bid = blockIdx.x;

    if (bid < EIF_BLOCKS) {
        // ---- eIF / target_if path: one (row, chunk) per block ----
        const int row   = bid / CHUNKS;
        const int chunk = bid % CHUNKS;
        if (mode_mask[row] != 1) return;   // masked row: zero contribution, zero traffic

        // mask count (for smooth scaling): 2-warp ballot, L2-hot mask
        int mybit = (tid < ROWS) ? (mode_mask[tid] == 1) : 0;
        unsigned bal = __ballot_sync(0xffffffffu, mybit);
        if ((tid >> 5) < 2 && (tid & 31) == 0) cnt2[tid >> 5] = __popc(bal);

        const size_t row_off = (size_t)row * Tdim;
        const float4* __restrict__ e4 = (const float4*)(eIF + row_off);
        const float4* __restrict__ t4 = (const float4*)(tif + row_off);
        const float*  __restrict__ er = eIF + row_off;

        const int vbase = chunk * VEC_PER_CHUNK;
        float acc_if = 0.0f, acc_sm = 0.0f;

        #pragma unroll 8
        for (int i = 0; i < EIF_ITERS; i++) {
            const int v = vbase + i * THREADS + tid;
            const float4 e  = __ldcs(e4 + v);   // streaming: evict-first
            const float4 tf = __ldcs(t4 + v);

            float dx = e.x - tf.x, dy = e.y - tf.y, dz = e.z - tf.z, dw = e.w - tf.w;
            acc_if += dx * dx + dy * dy + dz * dz + dw * dw;

            float d1 = e.y - e.x, d2 = e.z - e.y, d3 = e.w - e.z;
            acc_sm += d1 * d1 + d2 * d2 + d3 * d3;

            // neighbor e[t+4]: next lane's e.x, scalar patch at warp edge
            const int t = v * 4;
            float nx = __shfl_down_sync(0xffffffffu, e.x, 1);
            if ((tid & 31) == 31 && (t + 4 < Tdim)) nx = __ldcs(er + t + 4);
            if (t + 4 < Tdim) { float d4 = nx - e.w; acc_sm += d4 * d4; }
        }

        acc_if = block_reduce(acc_if, sm);   // internal syncthreads publish cnt2 too
        acc_sm = block_reduce(acc_sm, sm);

        if (tid == 0) {
            const float count = (float)(cnt2[0] + cnt2[1]);   // >0 (this row active)
            const float si = acc_if * (1.0f / 16777216.0f);   // / (B*N*T) = 2^-24, exact
            const float ss = acc_sm / (262143.0f * count);    // / ((T-1)*count)
            pdl_wait();    // zero_out_kernel complete; out[] zeroed
            atomicAdd(out + 2, si);
            atomicAdd(out + 3, ss);
            atomicAdd(out + 0, 0.5f * si + 0.1f * ss);
        }
    } else {
        // ---- recon path: grid-stride over B*T with float4 ----
        const int rb = bid - EIF_BLOCKS;
        const float4* __restrict__ a = (const float4*)rr;
        const float4* __restrict__ b = (const float4*)ri;
        const float4* __restrict__ c = (const float4*)tr;
        const float4* __restrict__ d = (const float4*)ti;

        float acc = 0.0f;
        #pragma unroll
        for (int j = 0; j < RECON_ITERS; j++) {
            const int v = rb * THREADS + tid + j * (RECON_BLOCKS * THREADS);
            const float4 xr = __ldcs(a + v), xt = __ldcs(c + v);
            const float4 yr = __ldcs(b + v), yt = __ldcs(d + v);
            float d0 = xr.x - xt.x, d1 = xr.y - xt.y, d2 = xr.z - xt.z, d3 = xr.w - xt.w;
            acc += d0 * d0 + d1 * d1 + d2 * d2 + d3 * d3;
            float e0 = yr.x - yt.x, e1 = yr.y - yt.y, e2 = yr.z - yt.z, e3 = yr.w - yt.w;
            acc += e0 * e0 + e1 * e1 + e2 * e2 + e3 * e3;
        }
        acc = block_reduce(acc, sm);

        if (tid == 0) {
            const float sr = acc * (1.0f / 2097152.0f);       // / (B*T) = 2^-21, exact
            pdl_wait();
            atomicAdd(out + 1, sr);
            atomicAdd(out + 0, sr);
        }
    }
}

extern "C" void kernel_launch(void* const* d_in, const int* in_sizes, int n_in,
                              void* d_out, int out_size)
{
    const float* recon_real  = (const float*)d_in[0];
    const float* recon_imag  = (const float*)d_in[1];
    const float* target_real = (const float*)d_in[2];
    const float* target_imag = (const float*)d_in[3];
    const float* eIF         = (const float*)d_in[4];
    const float* target_if   = (const float*)d_in[5];
    const int*   mode_mask   = (const int*)d_in[6];
    float* out = (float*)d_out;

    // Primary: zero out[]. Its launch_dependents fires at instruction 0.
    zero_out_kernel<<<1, 32>>>(out);

    // Dependent: main kernel, launched with PDL so it starts immediately;
    // ordering vs the zeroing is enforced by pdl_wait before the atomics.
    cudaLaunchConfig_t cfg = {};
    cfg.gridDim  = dim3(EIF_BLOCKS + RECON_BLOCKS);
    cfg.blockDim = dim3(THREADS);
    cfg.dynamicSmemBytes = 0;
    cfg.stream = 0;
    cudaLaunchAttribute attr[1];
    attr[0].id = cudaLaunchAttributeProgrammaticStreamSerialization;
    attr[0].val.programmaticStreamSerializationAllowed = 1;
    cfg.attrs = attr;
    cfg.numAttrs = 1;
    cudaLaunchKernelEx(&cfg, loss_main_kernel,
                       recon_real, recon_imag, target_real, target_imag,
                       eIF, target_if, mode_mask, out);
}

// round 16
// speedup vs baseline: 1.1983x; 1.1983x over previous
#include <cuda_runtime.h>

#define Bdim 8
#define Ndim 8
#define Tdim 262144
#define ROWS (Bdim * Ndim)            // 64
#define CHUNKS 16                     // chunks per eIF row
#define EIF_BLOCKS (ROWS * CHUNKS)    // 1024
#define RECON_BLOCKS 256
#define THREADS 256
#define VEC_PER_CHUNK (Tdim / CHUNKS / 4)          // 4096 float4 per chunk
#define EIF_ITERS (VEC_PER_CHUNK / THREADS)        // 16
#define RECON_VEC (Bdim * Tdim / 4)                // 524288 float4 per array
#define RECON_ITERS (RECON_VEC / (RECON_BLOCKS * THREADS))  // 8

__device__ __forceinline__ void pdl_launch_dependents() {
    asm volatile("griddepcontrol.launch_dependents;" ::: "memory");
}
__device__ __forceinline__ void pdl_wait() {
    asm volatile("griddepcontrol.wait;" ::: "memory");
}

__device__ __forceinline__ float block_reduce(float v, float* sm) {
    #pragma unroll
    for (int o = 16; o > 0; o >>= 1) v += __shfl_down_sync(0xffffffffu, v, o);
    int warp = threadIdx.x >> 5;
    __syncthreads();
    if ((threadIdx.x & 31) == 0) sm[warp] = v;
    __syncthreads();
    if (warp == 0) {
        v = (threadIdx.x < (THREADS >> 5)) ? sm[threadIdx.x] : 0.0f;
        #pragma unroll
        for (int o = 4; o > 0; o >>= 1) v += __shfl_down_sync(0xffffffffu, v, o);
    }
    return v;
}

// Primary: zero the 4 outputs. launch_dependents FIRST so the main kernel
// launches immediately and this kernel's cost hides under it.
__global__ void zero_out_kernel(float* __restrict__ out) {
    pdl_launch_dependents();
    if (threadIdx.x < 4) out[threadIdx.x] = 0.0f;
}

__global__ void __launch_bounds__(THREADS, 6)
loss_main_kernel(const float* __restrict__ rr, const float* __restrict__ ri,
                 const float* __restrict__ tr, const float* __restrict__ ti,
                 const float* __restrict__ eIF, const float* __restrict__ tif,
                 const int* __restrict__ mode_mask, float* __restrict__ out)
{
    __shared__ float sm[THREADS / 32];
    __shared__ int cnt2[2];
    const int tid = threadIdx.x;
    const int bid = blockIdx.x;

    if (bid < EIF_BLOCKS) {
        // ---- eIF / target_if path: one (row, chunk) per block ----
        const int row   = bid / CHUNKS;
        const int chunk = bid % CHUNKS;
        if (mode_mask[row] != 1) return;   // masked row: zero contribution, zero traffic

        const size_t row_off = (size_t)row * Tdim;
        const float4* __restrict__ e4 = (const float4*)(eIF + row_off);
        const float4* __restrict__ t4 = (const float4*)(tif + row_off);
        const float*  __restrict__ er = eIF + row_off;

        const int vbase = chunk * VEC_PER_CHUNK;
        float acc_if = 0.0f, acc_sm = 0.0f;

        #pragma unroll
        for (int i = 0; i < EIF_ITERS; i++) {
            const int v = vbase + i * THREADS + tid;
            const float4 e  = e4[v];
            const float4 tf = t4[v];

            float dx = e.x - tf.x, dy = e.y - tf.y, dz = e.z - tf.z, dw = e.w - tf.w;
            acc_if += dx * dx + dy * dy + dz * dz + dw * dw;

            float d1 = e.y - e.x, d2 = e.z - e.y, d3 = e.w - e.z;
            acc_sm += d1 * d1 + d2 * d2 + d3 * d3;

            // neighbor e[t+4]: independent predicated L1-hit scalar load
            // (same/adjacent line as this block's float4 loads) -- no shfl,
            // no cross-lane dependency, loads batch freely.
            const int t = v * 4;
            if (t + 4 < Tdim) {
                float nx = er[t + 4];
                float d4 = nx - e.w;
                acc_sm += d4 * d4;
            }
        }

        // mask count (for smooth scaling): 2-warp ballot, AFTER the hot loop
        // so streaming starts at block entry. L2-hot mask.
        int mybit = (tid < ROWS) ? (mode_mask[tid] == 1) : 0;
        unsigned bal = __ballot_sync(0xffffffffu, mybit);
        if ((tid >> 5) < 2 && (tid & 31) == 0) cnt2[tid >> 5] = __popc(bal);

        acc_if = block_reduce(acc_if, sm);   // internal syncthreads publish cnt2 too
        acc_sm = block_reduce(acc_sm, sm);

        if (tid == 0) {
            const float count = (float)(cnt2[0] + cnt2[1]);   // >0 (this row active)
            const float si = acc_if * (1.0f / 16777216.0f);   // / (B*N*T) = 2^-24, exact
            const float ss = acc_sm / (262143.0f * count);    // / ((T-1)*count)
            pdl_wait();    // zero_out_kernel complete; out[] zeroed
            atomicAdd(out + 2, si);
            atomicAdd(out + 3, ss);
            atomicAdd(out + 0, 0.5f * si + 0.1f * ss);
        }
    } else {
        // ---- recon path: grid-stride over B*T with float4 ----
        const int rb = bid - EIF_BLOCKS;
        const float4* __restrict__ a = (const float4*)rr;
        const float4* __restrict__ b = (const float4*)ri;
        const float4* __restrict__ c = (const float4*)tr;
        const float4* __restrict__ d = (const float4*)ti;

        float acc = 0.0f;
        #pragma unroll
        for (int j = 0; j < RECON_ITERS; j++) {
            const int v = rb * THREADS + tid + j * (RECON_BLOCKS * THREADS);
            const float4 xr = a[v], xt = c[v];
            const float4 yr = b[v], yt = d[v];
            float d0 = xr.x - xt.x, d1 = xr.y - xt.y, d2 = xr.z - xt.z, d3 = xr.w - xt.w;
            acc += d0 * d0 + d1 * d1 + d2 * d2 + d3 * d3;
            float e0 = yr.x - yt.x, e1 = yr.y - yt.y, e2 = yr.z - yt.z, e3 = yr.w - yt.w;
            acc += e0 * e0 + e1 * e1 + e2 * e2 + e3 * e3;
        }
        acc = block_reduce(acc, sm);

        if (tid == 0) {
            const float sr = acc * (1.0f / 2097152.0f);       // / (B*T) = 2^-21, exact
            pdl_wait();
            atomicAdd(out + 1, sr);
            atomicAdd(out + 0, sr);
        }
    }
}

extern "C" void kernel_launch(void* const* d_in, const int* in_sizes, int n_in,
                              void* d_out, int out_size)
{
    const float* recon_real  = (const float*)d_in[0];
    const float* recon_imag  = (const float*)d_in[1];
    const float* target_real = (const float*)d_in[2];
    const float* target_imag = (const float*)d_in[3];
    const float* eIF         = (const float*)d_in[4];
    const float* target_if   = (const float*)d_in[5];
    const int*   mode_mask   = (const int*)d_in[6];
    float* out = (float*)d_out;

    // Primary: zero out[]. Its launch_dependents fires at instruction 0.
    zero_out_kernel<<<1, 32>>>(out);

    // Dependent: main kernel, launched with PDL so it starts immediately;
    // ordering vs the zeroing is enforced by pdl_wait before the atomics.
    cudaLaunchConfig_t cfg = {};
    cfg.gridDim  = dim3(EIF_BLOCKS + RECON_BLOCKS);
    cfg.blockDim = dim3(THREADS);
    cfg.dynamicSmemBytes = 0;
    cfg.stream = 0;
    cudaLaunchAttribute attr[1];
    attr[0].id = cudaLaunchAttributeProgrammaticStreamSerialization;
    attr[0].val.programmaticStreamSerializationAllowed = 1;
    cfg.attrs = attr;
    cfg.numAttrs = 1;
    cudaLaunchKernelEx(&cfg, loss_main_kernel,
                       recon_real, recon_imag, target_real, target_imag,
                       eIF, target_if, mode_mask, out);
}